// round 13
// baseline (speedup 1.0000x reference)
#include <cuda_runtime.h>

#define N 256
#define BIG 1e9f
#define FINF __int_as_float(0x7F800000)
#define CROWS 216   // rows of C cached in SMEM; rest served by L2

// Branchless monotone float -> uint key (order-preserving) and inverse.
__device__ __forceinline__ unsigned fkey(float f) {
    const unsigned b = __float_as_uint(f);
    return b ^ (unsigned)(((int)b >> 31) | 0x80000000);
}
__device__ __forceinline__ float unfkey(unsigned k) {
    return __uint_as_float(k ^ (unsigned)((~(int)k >> 31) | 0x80000000));
}

// Column ownership (0-based): lane owns col(k) = 64*(k>>1) + 2*lane + (k&1),
// k = 0..7 (4 adjacent pairs -> float2 loads, conflict-free LDS.64).
// Inverse: lane = (c0>>1)&31, k = ((c0>>6)<<1)|(c0&1).
__device__ __forceinline__ int colof(int lane, int k) {
    return 64 * (k >> 1) + 2 * lane + (k & 1);
}

// Jonker-Volgenant LAP (algorithm validated R6-R9):
//   phase 1: column reduction + SMEM row cache fill
//   phase 2: serial greedy assignment
//   phase 2b: bounded 3-pass augmenting row reduction
//   phase 3: single-warp absolute-distance Dijkstra augmentation
// R12 (= R10 resubmit after two infra flakes): per-row
// meta[k] = jc | (p[jc]<<9) precompute (p is loop-invariant within a row)
// lets the local argmin run as a (val, meta) pairwise tree — removing the
// post-tree eq-select chain and the p[jc] LDS from the serial tail;
// branchless fkey.
__global__ __launch_bounds__(256, 1)
void lap_jv12(const float* __restrict__ C, float* __restrict__ out) {
    extern __shared__ float smem_dyn[];
    float* Ccache = smem_dyn;                      // [CROWS][256]
    float* u0     = Ccache + CROWS * 256;          // [N+1]
    float* vinit  = u0 + (N + 1);                  // [N+1]
    int*   p      = (int*)(vinit + (N + 1));       // [N+1] col -> row (0=free)
    int*   way    = p + (N + 1);                   // [N+1]
    int*   rmin   = way + (N + 1);                 // [N+1]
    int*   xrow   = rmin + (N + 1);                // [N+1]
    int*   lista  = xrow + (N + 1);                // [N]
    int*   listb  = lista + N;                     // [N]
    int*   sh_nfree = listb + N;                   // [1]

    const int tid = threadIdx.x;

    // ---- phase 1: column reduction + fill SMEM row cache (coalesced)
    {
        float best = C[tid];
        int   bi   = 0;
        Ccache[tid] = best;                        // row 0
        #pragma unroll 8
        for (int i = 1; i < N; ++i) {
            const float c = C[i * N + tid];
            if (i < CROWS) Ccache[i * 256 + tid] = c;
            if (c < best) { best = c; bi = i; }
        }
        vinit[tid + 1] = best;
        rmin[tid + 1]  = bi + 1;
        u0[tid + 1]    = 0.0f;
        p[tid + 1]     = 0;
        xrow[tid + 1]  = 0;
        if (tid == 0) { u0[0] = 0.0f; vinit[0] = 0.0f; p[0] = 0; xrow[0] = 0; }
    }
    __syncthreads();

    // ---- phase 2: greedy assignment (serial, short)
    if (tid == 0) {
        for (int j = 1; j <= N; ++j) {
            const int r = rmin[j];
            if (xrow[r] == 0) { xrow[r] = j; p[j] = r; }
        }
        int nf = 0;
        for (int r = 1; r <= N; ++r) if (xrow[r] == 0) lista[nf++] = r;
        *sh_nfree = nf;
    }
    __syncthreads();

    if (tid < 32) {
        const int lane = tid;
        float v[8], dist[8], mark[8], vsave[8];
        #pragma unroll
        for (int k = 0; k < 8; ++k) v[k] = vinit[colof(lane, k) + 1];

        // ---- phase 2b: bounded ARR, 3 passes, kicked rows -> next list
        int nf_cur = *sh_nfree;
        int* cur  = lista;
        int* nxt  = listb;
        #pragma unroll 1
        for (int pass = 0; pass < 3; ++pass) {
            int nf_nxt = 0;
            for (int kq = 0; kq < nf_cur; ++kq) {
                const int i = cur[kq];

                // warp scan of row i: min1 (argmin col) + min2 of C - v
                float d[8];
                if (i <= CROWS) {
                    const float* rs = Ccache + (i - 1) * 256 + 2 * lane;
                    #pragma unroll
                    for (int s = 0; s < 4; ++s) {
                        const float2 t = *(const float2*)(rs + 64 * s);
                        d[2 * s]     = t.x - v[2 * s];
                        d[2 * s + 1] = t.y - v[2 * s + 1];
                    }
                } else {
                    const float* rowp = C + (i - 1) * N + 2 * lane;
                    #pragma unroll
                    for (int s = 0; s < 4; ++s) {
                        const float2 t = __ldg((const float2*)(rowp + 64 * s));
                        d[2 * s]     = t.x - v[2 * s];
                        d[2 * s + 1] = t.y - v[2 * s + 1];
                    }
                }
                float m1 = d[0], m2 = BIG;
                int bk = 0;
                #pragma unroll
                for (int s = 1; s < 8; ++s) {
                    if (d[s] < m1)      { m2 = m1; m1 = d[s]; bk = s; }
                    else if (d[s] < m2) { m2 = d[s]; }
                }
                int jmin = colof(lane, bk) + 1;
                #pragma unroll
                for (int off = 16; off; off >>= 1) {
                    const float om1 = __shfl_xor_sync(0xFFFFFFFFu, m1, off);
                    const int   oj  = __shfl_xor_sync(0xFFFFFFFFu, jmin, off);
                    const float om2 = __shfl_xor_sync(0xFFFFFFFFu, m2, off);
                    m2 = fminf(fminf(m2, om2), fmaxf(m1, om1));
                    if (om1 < m1) { m1 = om1; jmin = oj; }
                }

                const int   i0    = p[jmin];          // uniform
                const float delta = m2 - m1;
                if (delta > 0.0f || i0 == 0) {
                    const int c0 = jmin - 1;
                    if (((c0 >> 1) & 31) == lane)
                        v[((c0 >> 6) << 1) | (c0 & 1)] -= delta;
                    if (lane == 0) { u0[i] = m2; p[jmin] = i; }
                    if (i0 != 0) {                    // kicked -> next pass
                        if (lane == 0) nxt[nf_nxt] = i0;
                        ++nf_nxt;
                    }
                } else {                              // tie on occupied col
                    if (lane == 0) nxt[nf_nxt] = i;
                    ++nf_nxt;
                }
                __syncwarp();
            }
            nf_cur = nf_nxt;
            int* t = cur; cur = nxt; nxt = t;
        }

        // ---- phase 3: Dijkstra augmentation per remaining free row
        const int nf = nf_cur;
        for (int fr = 0; fr < nf; ++fr) {
            const int i = cur[fr];

            // per-row meta: jc | (p[jc] << 9); p is fixed during this row
            int meta[8];
            #pragma unroll
            for (int k = 0; k < 8; ++k) {
                const int jc = colof(lane, k) + 1;
                meta[k] = jc | (p[jc] << 9);
            }
            #pragma unroll
            for (int k = 0; k < 8; ++k) dist[k] = BIG;
            unsigned usedmask = 0;
            float Dsum = 0.0f;
            int j0 = 0, i0 = i, jfree;
            if (lane == 0) p[0] = i;

            for (;;) {
                // row loads first (v2); bookkeeping in their shadow
                float cc[8];
                if (i0 <= CROWS) {
                    const float* rs = Ccache + (i0 - 1) * 256 + 2 * lane;
                    #pragma unroll
                    for (int s = 0; s < 4; ++s) {
                        const float2 t = *(const float2*)(rs + 64 * s);
                        cc[2 * s] = t.x; cc[2 * s + 1] = t.y;
                    }
                } else {
                    const float* rowp = C + (i0 - 1) * N + 2 * lane;
                    #pragma unroll
                    for (int s = 0; s < 4; ++s) {
                        const float2 t = __ldg((const float2*)(rowp + 64 * s));
                        cc[2 * s] = t.x; cc[2 * s + 1] = t.y;
                    }
                }
                const float s0 = Dsum - u0[i0];

                // mark popped column j0: freeze value, poison v, kill dist
                if (j0) {
                    const int c0 = j0 - 1;
                    if (((c0 >> 1) & 31) == lane) {
                        const int k = ((c0 >> 6) << 1) | (c0 & 1);
                        usedmask |= 1u << k;
                        mark[k]  = Dsum;
                        vsave[k] = v[k];
                        v[k]     = -FINF;   // cur_d becomes +INF forever
                        dist[k]  = FINF;
                    }
                }

                // update loop: poisoned cols give +INF, no used test needed
                #pragma unroll
                for (int k = 0; k < 8; ++k) {
                    const float cur_d = (cc[k] - v[k]) + s0;
                    if (cur_d < dist[k]) {
                        dist[k] = cur_d;
                        way[colof(lane, k) + 1] = j0;
                    }
                }

                // local argmin: (val, meta) pairwise tree, 3 levels
                float va = fminf(dist[0], dist[1]);
                float vb = fminf(dist[2], dist[3]);
                float vc = fminf(dist[4], dist[5]);
                float vd = fminf(dist[6], dist[7]);
                int ma = (dist[1] < dist[0]) ? meta[1] : meta[0];
                int mb = (dist[3] < dist[2]) ? meta[3] : meta[2];
                int mc = (dist[5] < dist[4]) ? meta[5] : meta[4];
                int md = (dist[7] < dist[6]) ? meta[7] : meta[6];
                const float vab = fminf(va, vb), vcd = fminf(vc, vd);
                const int   mab = (vb < va) ? mb : ma;
                const int   mcd = (vd < vc) ? md : mc;
                const float bv  = fminf(vab, vcd);
                const int   bm  = (vcd < vab) ? mcd : mab;

                // warp argmin + coherent winner broadcast
                const unsigned key  = fkey(bv);
                const unsigned kmin = __reduce_min_sync(0xFFFFFFFFu, key);
                const unsigned packed = (key == kmin) ? (unsigned)bm : 0u;
                const unsigned win = __reduce_max_sync(0xFFFFFFFFu, packed);
                Dsum = unfkey(kmin);
                j0 = (int)(win & 511u);
                i0 = (int)(win >> 9);
                if (i0 == 0) { jfree = j0; break; }
            }

            // end-of-row dual updates; restore poisoned v from vsave
            const float Dfinal = Dsum;
            #pragma unroll
            for (int k = 0; k < 8; ++k) {
                if ((usedmask >> k) & 1u) {
                    const float amt = Dfinal - mark[k];
                    v[k] = vsave[k] - amt;
                    u0[meta[k] >> 9] += amt;          // p[jc] at row start: the
                }                                     // matched row, distinct
            }
            if (lane == 0) u0[i] += Dfinal;
            __syncwarp();

            if (lane == 0) {                          // augment path
                int jj = jfree;
                while (jj != 0) { const int j1 = way[jj]; p[jj] = p[j1]; jj = j1; }
            }
            __syncwarp();
        }
    }
    __syncthreads();

    // ---- output: 0/1 labelling
    {
        const float4 z = make_float4(0.f, 0.f, 0.f, 0.f);
        for (int idx = tid; idx < N * N / 4; idx += 256) ((float4*)out)[idx] = z;
    }
    __syncthreads();
    {
        const int col = tid;                          // 0-based column
        const int r   = p[col + 1] - 1;               // 0-based matched row
        out[r * N + col] = 1.0f;
    }
}

// Dynamic SMEM size: C cache + solver state
#define SMEM_BYTES (CROWS * 256 * 4 + 2 * (N + 1) * 4 + 4 * (N + 1) * 4 \
                    + 2 * N * 4 + 4)

extern "C" void kernel_launch(void* const* d_in, const int* in_sizes, int n_in,
                              void* d_out, int out_size) {
    (void)in_sizes; (void)n_in; (void)out_size;
    cudaFuncSetAttribute(lap_jv12, cudaFuncAttributeMaxDynamicSharedMemorySize,
                         SMEM_BYTES);
    lap_jv12<<<1, 256, SMEM_BYTES>>>((const float*)d_in[0], (float*)d_out);
}

// round 15
// speedup vs baseline: 1.0842x; 1.0842x over previous
#include <cuda_runtime.h>

#define N 256
#define BIG 1e9f
#define FINF __int_as_float(0x7F800000)
#define INF_KEY 0x7F800000            // +inf raw bits; max among valid keys
#define CROWS 216   // rows of C cached in SMEM; rest served by L2

// Column ownership (0-based): lane owns col(k) = 64*(k>>1) + 2*lane + (k&1),
// k = 0..7 (4 adjacent pairs -> float2 loads, conflict-free LDS.64).
__device__ __forceinline__ int colof(int lane, int k) {
    return 64 * (k >> 1) + 2 * lane + (k & 1);
}

// Jonker-Volgenant LAP (algorithm validated R6-R9):
//   phase 1: column reduction + SMEM row cache fill
//   phase 2: serial greedy assignment
//   phase 2b: bounded 3-pass augmenting row reduction
//   phase 3: single-warp absolute-distance Dijkstra augmentation
// R15: int raw-bit dist keys (fkey deleted from chain; IMNMX update/tree;
// distances >= -1e-7 so signed raw-bit order is correct up to rounding
// noise, covered by the unique-optimum argument). Index recovery uses the
// R9-proven priority select chain (no synthesized indices). Defensive hard
// bounds on the pop loop and augmentation walk turn any residual hang into
// a rel_err failure instead of a timeout.
__global__ __launch_bounds__(256, 1)
void lap_jv15(const float* __restrict__ C, float* __restrict__ out) {
    extern __shared__ float smem_dyn[];
    float* Ccache = smem_dyn;                      // [CROWS][256]
    float* u0     = Ccache + CROWS * 256;          // [N+1]
    float* vinit  = u0 + (N + 1);                  // [N+1]
    int*   p      = (int*)(vinit + (N + 1));       // [N+1] col -> row (0=free)
    int*   way    = p + (N + 1);                   // [N+1]
    int*   rmin   = way + (N + 1);                 // [N+1]
    int*   xrow   = rmin + (N + 1);                // [N+1]
    int*   lista  = xrow + (N + 1);                // [N]
    int*   listb  = lista + N;                     // [N]
    int*   sh_nfree = listb + N;                   // [1]

    const int tid = threadIdx.x;

    // ---- phase 1: column reduction + fill SMEM row cache (coalesced)
    {
        float best = C[tid];
        int   bi   = 0;
        Ccache[tid] = best;                        // row 0
        #pragma unroll 8
        for (int i = 1; i < N; ++i) {
            const float c = C[i * N + tid];
            if (i < CROWS) Ccache[i * 256 + tid] = c;
            if (c < best) { best = c; bi = i; }
        }
        vinit[tid + 1] = best;
        rmin[tid + 1]  = bi + 1;
        u0[tid + 1]    = 0.0f;
        p[tid + 1]     = 0;
        xrow[tid + 1]  = 0;
        if (tid == 0) { u0[0] = 0.0f; vinit[0] = 0.0f; p[0] = 0; xrow[0] = 0; }
    }
    __syncthreads();

    // ---- phase 2: greedy assignment (serial, short)
    if (tid == 0) {
        for (int j = 1; j <= N; ++j) {
            const int r = rmin[j];
            if (xrow[r] == 0) { xrow[r] = j; p[j] = r; }
        }
        int nf = 0;
        for (int r = 1; r <= N; ++r) if (xrow[r] == 0) lista[nf++] = r;
        *sh_nfree = nf;
    }
    __syncthreads();

    if (tid < 32) {
        const int lane = tid;
        float v[8], mark[8], vsave[8];
        int   dist[8];                              // raw fp32 bits, signed cmp
        #pragma unroll
        for (int k = 0; k < 8; ++k) v[k] = vinit[colof(lane, k) + 1];

        // ---- phase 2b: bounded ARR, 3 passes, kicked rows -> next list
        int nf_cur = *sh_nfree;
        int* cur  = lista;
        int* nxt  = listb;
        #pragma unroll 1
        for (int pass = 0; pass < 3; ++pass) {
            int nf_nxt = 0;
            for (int kq = 0; kq < nf_cur; ++kq) {
                const int i = cur[kq];

                // warp scan of row i: min1 (argmin col) + min2 of C - v
                float d[8];
                if (i <= CROWS) {
                    const float* rs = Ccache + (i - 1) * 256 + 2 * lane;
                    #pragma unroll
                    for (int s = 0; s < 4; ++s) {
                        const float2 t = *(const float2*)(rs + 64 * s);
                        d[2 * s]     = t.x - v[2 * s];
                        d[2 * s + 1] = t.y - v[2 * s + 1];
                    }
                } else {
                    const float* rowp = C + (i - 1) * N + 2 * lane;
                    #pragma unroll
                    for (int s = 0; s < 4; ++s) {
                        const float2 t = __ldg((const float2*)(rowp + 64 * s));
                        d[2 * s]     = t.x - v[2 * s];
                        d[2 * s + 1] = t.y - v[2 * s + 1];
                    }
                }
                float m1 = d[0], m2 = BIG;
                int bk = 0;
                #pragma unroll
                for (int s = 1; s < 8; ++s) {
                    if (d[s] < m1)      { m2 = m1; m1 = d[s]; bk = s; }
                    else if (d[s] < m2) { m2 = d[s]; }
                }
                int jmin = colof(lane, bk) + 1;
                #pragma unroll
                for (int off = 16; off; off >>= 1) {
                    const float om1 = __shfl_xor_sync(0xFFFFFFFFu, m1, off);
                    const int   oj  = __shfl_xor_sync(0xFFFFFFFFu, jmin, off);
                    const float om2 = __shfl_xor_sync(0xFFFFFFFFu, m2, off);
                    m2 = fminf(fminf(m2, om2), fmaxf(m1, om1));
                    if (om1 < m1) { m1 = om1; jmin = oj; }
                }

                const int   i0    = p[jmin];          // uniform
                const float delta = m2 - m1;
                if (delta > 0.0f || i0 == 0) {
                    const int c0 = jmin - 1;
                    if (((c0 >> 1) & 31) == lane)
                        v[((c0 >> 6) << 1) | (c0 & 1)] -= delta;
                    if (lane == 0) { u0[i] = m2; p[jmin] = i; }
                    if (i0 != 0) {                    // kicked -> next pass
                        if (lane == 0) nxt[nf_nxt] = i0;
                        ++nf_nxt;
                    }
                } else {                              // tie on occupied col
                    if (lane == 0) nxt[nf_nxt] = i;
                    ++nf_nxt;
                }
                __syncwarp();
            }
            nf_cur = nf_nxt;
            int* t = cur; cur = nxt; nxt = t;
        }

        // ---- phase 3: Dijkstra augmentation per remaining free row
        const int BIG_KEY = __float_as_int(BIG);
        const int nf = nf_cur;
        for (int fr = 0; fr < nf; ++fr) {
            const int i = cur[fr];
            #pragma unroll
            for (int k = 0; k < 8; ++k) dist[k] = BIG_KEY;
            unsigned usedmask = 0;
            float Dsum = 0.0f;
            int j0 = 0, i0 = i, jfree = 0;
            if (lane == 0) p[0] = i;

            // bounded: a row needs <= 257 pops; 320 is a hang-proof ceiling
            for (int step = 0; step < 320; ++step) {
                // row loads first (v2); bookkeeping in their shadow
                float cc[8];
                if (i0 <= CROWS) {
                    const float* rs = Ccache + (i0 - 1) * 256 + 2 * lane;
                    #pragma unroll
                    for (int s = 0; s < 4; ++s) {
                        const float2 t = *(const float2*)(rs + 64 * s);
                        cc[2 * s] = t.x; cc[2 * s + 1] = t.y;
                    }
                } else {
                    const float* rowp = C + (i0 - 1) * N + 2 * lane;
                    #pragma unroll
                    for (int s = 0; s < 4; ++s) {
                        const float2 t = __ldg((const float2*)(rowp + 64 * s));
                        cc[2 * s] = t.x; cc[2 * s + 1] = t.y;
                    }
                }
                const float s0 = Dsum - u0[i0];

                // mark popped column j0: freeze value, poison v, kill dist
                if (j0) {
                    const int c0 = j0 - 1;
                    if (((c0 >> 1) & 31) == lane) {
                        const int k = ((c0 >> 6) << 1) | (c0 & 1);
                        usedmask |= 1u << k;
                        mark[k]  = Dsum;
                        vsave[k] = v[k];
                        v[k]     = -FINF;   // cur_d becomes +INF forever
                        dist[k]  = INF_KEY;
                    }
                }

                // update: raw-bit keys, IMNMX; way predicate vs old dist
                #pragma unroll
                for (int k = 0; k < 8; ++k) {
                    const int ck = __float_as_int((cc[k] - v[k]) + s0);
                    if (ck < dist[k]) way[colof(lane, k) + 1] = j0;
                    dist[k] = min(dist[k], ck);
                }

                // min tree on int keys (IMNMX.S32)
                const int t0 = min(dist[0], dist[1]);
                const int t1 = min(dist[2], dist[3]);
                const int t2 = min(dist[4], dist[5]);
                const int t3 = min(dist[6], dist[7]);
                const int bvk = min(min(t0, t1), min(t2, t3));

                // warp argmin (signed redux); R9-proven priority index chain
                const int kmin = __reduce_min_sync(0xFFFFFFFFu, bvk);

                int bk = 7;
                #pragma unroll
                for (int k = 6; k >= 0; --k) bk = (dist[k] == bvk) ? k : bk;
                const int jc = colof(lane, bk) + 1;
                const int ic = p[jc];                 // hidden under redux

                const unsigned packed =
                    (bvk == kmin) ? (unsigned)(jc | (ic << 9)) : 0u;
                const unsigned win = __reduce_max_sync(0xFFFFFFFFu, packed);
                Dsum = __int_as_float(kmin);
                j0 = (int)(win & 511u);
                i0 = (int)(win >> 9);
                if (i0 == 0) { jfree = j0; break; }
            }

            // end-of-row dual updates; restore poisoned v from vsave
            const float Dfinal = Dsum;
            #pragma unroll
            for (int k = 0; k < 8; ++k) {
                if ((usedmask >> k) & 1u) {
                    const float amt = Dfinal - mark[k];
                    v[k] = vsave[k] - amt;
                    u0[p[colof(lane, k) + 1]] += amt; // distinct rows: safe
                }
            }
            if (lane == 0) u0[i] += Dfinal;
            __syncwarp();

            if (lane == 0) {                          // augment path (bounded)
                int jj = jfree;
                int guard = 0;
                while (jj != 0 && ++guard <= 300) {
                    const int j1 = way[jj]; p[jj] = p[j1]; jj = j1;
                }
            }
            __syncwarp();
        }
    }
    __syncthreads();

    // ---- output: 0/1 labelling
    {
        const float4 z = make_float4(0.f, 0.f, 0.f, 0.f);
        for (int idx = tid; idx < N * N / 4; idx += 256) ((float4*)out)[idx] = z;
    }
    __syncthreads();
    {
        const int col = tid;                          // 0-based column
        const int r   = p[col + 1] - 1;               // 0-based matched row
        if (r >= 0 && r < N) out[r * N + col] = 1.0f;
    }
}

// Dynamic SMEM size: C cache + solver state
#define SMEM_BYTES (CROWS * 256 * 4 + 2 * (N + 1) * 4 + 4 * (N + 1) * 4 \
                    + 2 * N * 4 + 4)

extern "C" void kernel_launch(void* const* d_in, const int* in_sizes, int n_in,
                              void* d_out, int out_size) {
    (void)in_sizes; (void)n_in; (void)out_size;
    cudaFuncSetAttribute(lap_jv15, cudaFuncAttributeMaxDynamicSharedMemorySize,
                         SMEM_BYTES);
    lap_jv15<<<1, 256, SMEM_BYTES>>>((const float*)d_in[0], (float*)d_out);
}

// round 16
// speedup vs baseline: 1.0858x; 1.0015x over previous
#include <cuda_runtime.h>

#define N 256
#define BIG 1e9f
#define FINF __int_as_float(0x7F800000)
#define INF_KEY 0x7F800000            // +inf raw bits; max among valid keys
#define CROWS 216   // rows of C cached in SMEM; rest served by L2

// Column ownership (0-based): lane owns col(k) = 64*(k>>1) + 2*lane + (k&1),
// k = 0..7 (4 adjacent pairs -> float2 loads, conflict-free LDS.64).
__device__ __forceinline__ int colof(int lane, int k) {
    return 64 * (k >> 1) + 2 * lane + (k & 1);
}

// Jonker-Volgenant LAP (algorithm validated R6-R15):
//   phase 1: column reduction + SMEM row cache fill
//   phase 2: serial greedy assignment
//   phase 2b: bounded augmenting row reduction (now 4 passes)
//   phase 3: single-warp absolute-distance Dijkstra augmentation with int
//            raw-bit dist keys (R15-validated)
// R16: s1[k] = (Dsum - u0[i0]) - v[k] precomputed in the row-load shadow,
// leaving a single FADD after the load (reassociation of the same class as
// the accepted R8 refold); ARR 4 passes.
__global__ __launch_bounds__(256, 1)
void lap_jv16(const float* __restrict__ C, float* __restrict__ out) {
    extern __shared__ float smem_dyn[];
    float* Ccache = smem_dyn;                      // [CROWS][256]
    float* u0     = Ccache + CROWS * 256;          // [N+1]
    float* vinit  = u0 + (N + 1);                  // [N+1]
    int*   p      = (int*)(vinit + (N + 1));       // [N+1] col -> row (0=free)
    int*   way    = p + (N + 1);                   // [N+1]
    int*   rmin   = way + (N + 1);                 // [N+1]
    int*   xrow   = rmin + (N + 1);                // [N+1]
    int*   lista  = xrow + (N + 1);                // [N]
    int*   listb  = lista + N;                     // [N]
    int*   sh_nfree = listb + N;                   // [1]

    const int tid = threadIdx.x;

    // ---- phase 1: column reduction + fill SMEM row cache (coalesced)
    {
        float best = C[tid];
        int   bi   = 0;
        Ccache[tid] = best;                        // row 0
        #pragma unroll 8
        for (int i = 1; i < N; ++i) {
            const float c = C[i * N + tid];
            if (i < CROWS) Ccache[i * 256 + tid] = c;
            if (c < best) { best = c; bi = i; }
        }
        vinit[tid + 1] = best;
        rmin[tid + 1]  = bi + 1;
        u0[tid + 1]    = 0.0f;
        p[tid + 1]     = 0;
        xrow[tid + 1]  = 0;
        if (tid == 0) { u0[0] = 0.0f; vinit[0] = 0.0f; p[0] = 0; xrow[0] = 0; }
    }
    __syncthreads();

    // ---- phase 2: greedy assignment (serial, short)
    if (tid == 0) {
        for (int j = 1; j <= N; ++j) {
            const int r = rmin[j];
            if (xrow[r] == 0) { xrow[r] = j; p[j] = r; }
        }
        int nf = 0;
        for (int r = 1; r <= N; ++r) if (xrow[r] == 0) lista[nf++] = r;
        *sh_nfree = nf;
    }
    __syncthreads();

    if (tid < 32) {
        const int lane = tid;
        float v[8], mark[8], vsave[8];
        int   dist[8];                              // raw fp32 bits, signed cmp
        #pragma unroll
        for (int k = 0; k < 8; ++k) v[k] = vinit[colof(lane, k) + 1];

        // ---- phase 2b: bounded ARR, 4 passes, kicked rows -> next list
        int nf_cur = *sh_nfree;
        int* cur  = lista;
        int* nxt  = listb;
        #pragma unroll 1
        for (int pass = 0; pass < 4; ++pass) {
            int nf_nxt = 0;
            for (int kq = 0; kq < nf_cur; ++kq) {
                const int i = cur[kq];

                // warp scan of row i: min1 (argmin col) + min2 of C - v
                float d[8];
                if (i <= CROWS) {
                    const float* rs = Ccache + (i - 1) * 256 + 2 * lane;
                    #pragma unroll
                    for (int s = 0; s < 4; ++s) {
                        const float2 t = *(const float2*)(rs + 64 * s);
                        d[2 * s]     = t.x - v[2 * s];
                        d[2 * s + 1] = t.y - v[2 * s + 1];
                    }
                } else {
                    const float* rowp = C + (i - 1) * N + 2 * lane;
                    #pragma unroll
                    for (int s = 0; s < 4; ++s) {
                        const float2 t = __ldg((const float2*)(rowp + 64 * s));
                        d[2 * s]     = t.x - v[2 * s];
                        d[2 * s + 1] = t.y - v[2 * s + 1];
                    }
                }
                float m1 = d[0], m2 = BIG;
                int bk = 0;
                #pragma unroll
                for (int s = 1; s < 8; ++s) {
                    if (d[s] < m1)      { m2 = m1; m1 = d[s]; bk = s; }
                    else if (d[s] < m2) { m2 = d[s]; }
                }
                int jmin = colof(lane, bk) + 1;
                #pragma unroll
                for (int off = 16; off; off >>= 1) {
                    const float om1 = __shfl_xor_sync(0xFFFFFFFFu, m1, off);
                    const int   oj  = __shfl_xor_sync(0xFFFFFFFFu, jmin, off);
                    const float om2 = __shfl_xor_sync(0xFFFFFFFFu, m2, off);
                    m2 = fminf(fminf(m2, om2), fmaxf(m1, om1));
                    if (om1 < m1) { m1 = om1; jmin = oj; }
                }

                const int   i0    = p[jmin];          // uniform
                const float delta = m2 - m1;
                if (delta > 0.0f || i0 == 0) {
                    const int c0 = jmin - 1;
                    if (((c0 >> 1) & 31) == lane)
                        v[((c0 >> 6) << 1) | (c0 & 1)] -= delta;
                    if (lane == 0) { u0[i] = m2; p[jmin] = i; }
                    if (i0 != 0) {                    // kicked -> next pass
                        if (lane == 0) nxt[nf_nxt] = i0;
                        ++nf_nxt;
                    }
                } else {                              // tie on occupied col
                    if (lane == 0) nxt[nf_nxt] = i;
                    ++nf_nxt;
                }
                __syncwarp();
            }
            nf_cur = nf_nxt;
            int* t = cur; cur = nxt; nxt = t;
        }

        // ---- phase 3: Dijkstra augmentation per remaining free row
        const int BIG_KEY = __float_as_int(BIG);
        const int nf = nf_cur;
        for (int fr = 0; fr < nf; ++fr) {
            const int i = cur[fr];
            #pragma unroll
            for (int k = 0; k < 8; ++k) dist[k] = BIG_KEY;
            unsigned usedmask = 0;
            float Dsum = 0.0f;
            int j0 = 0, i0 = i, jfree = 0;
            if (lane == 0) p[0] = i;

            // bounded: a row needs <= 257 pops; 320 is a hang-proof ceiling
            for (int step = 0; step < 320; ++step) {
                // row loads first (v2); everything below runs in their shadow
                float cc[8];
                if (i0 <= CROWS) {
                    const float* rs = Ccache + (i0 - 1) * 256 + 2 * lane;
                    #pragma unroll
                    for (int s = 0; s < 4; ++s) {
                        const float2 t = *(const float2*)(rs + 64 * s);
                        cc[2 * s] = t.x; cc[2 * s + 1] = t.y;
                    }
                } else {
                    const float* rowp = C + (i0 - 1) * N + 2 * lane;
                    #pragma unroll
                    for (int s = 0; s < 4; ++s) {
                        const float2 t = __ldg((const float2*)(rowp + 64 * s));
                        cc[2 * s] = t.x; cc[2 * s + 1] = t.y;
                    }
                }

                // shadow work 1: mark popped column j0
                if (j0) {
                    const int c0 = j0 - 1;
                    if (((c0 >> 1) & 31) == lane) {
                        const int k = ((c0 >> 6) << 1) | (c0 & 1);
                        usedmask |= 1u << k;
                        mark[k]  = Dsum;
                        vsave[k] = v[k];
                        v[k]     = -FINF;   // s1 becomes +INF forever
                        dist[k]  = INF_KEY;
                    }
                }

                // shadow work 2: per-lane shifted duals (independent of cc)
                const float s0 = Dsum - u0[i0];
                float s1[8];
                #pragma unroll
                for (int k = 0; k < 8; ++k) s1[k] = s0 - v[k];

                // post-load: ONE FADD per column, then IMNMX
                #pragma unroll
                for (int k = 0; k < 8; ++k) {
                    const int ck = __float_as_int(cc[k] + s1[k]);
                    if (ck < dist[k]) way[colof(lane, k) + 1] = j0;
                    dist[k] = min(dist[k], ck);
                }

                // min tree on int keys (IMNMX.S32)
                const int t0 = min(dist[0], dist[1]);
                const int t1 = min(dist[2], dist[3]);
                const int t2 = min(dist[4], dist[5]);
                const int t3 = min(dist[6], dist[7]);
                const int bvk = min(min(t0, t1), min(t2, t3));

                // warp argmin (signed redux); priority index chain (R9/R15)
                const int kmin = __reduce_min_sync(0xFFFFFFFFu, bvk);

                int bk = 7;
                #pragma unroll
                for (int k = 6; k >= 0; --k) bk = (dist[k] == bvk) ? k : bk;
                const int jc = colof(lane, bk) + 1;
                const int ic = p[jc];                 // hidden under redux

                const unsigned packed =
                    (bvk == kmin) ? (unsigned)(jc | (ic << 9)) : 0u;
                const unsigned win = __reduce_max_sync(0xFFFFFFFFu, packed);
                Dsum = __int_as_float(kmin);
                j0 = (int)(win & 511u);
                i0 = (int)(win >> 9);
                if (i0 == 0) { jfree = j0; break; }
            }

            // end-of-row dual updates; restore poisoned v from vsave
            const float Dfinal = Dsum;
            #pragma unroll
            for (int k = 0; k < 8; ++k) {
                if ((usedmask >> k) & 1u) {
                    const float amt = Dfinal - mark[k];
                    v[k] = vsave[k] - amt;
                    u0[p[colof(lane, k) + 1]] += amt; // distinct rows: safe
                }
            }
            if (lane == 0) u0[i] += Dfinal;
            __syncwarp();

            if (lane == 0) {                          // augment path (bounded)
                int jj = jfree;
                int guard = 0;
                while (jj != 0 && ++guard <= 300) {
                    const int j1 = way[jj]; p[jj] = p[j1]; jj = j1;
                }
            }
            __syncwarp();
        }
    }
    __syncthreads();

    // ---- output: 0/1 labelling
    {
        const float4 z = make_float4(0.f, 0.f, 0.f, 0.f);
        for (int idx = tid; idx < N * N / 4; idx += 256) ((float4*)out)[idx] = z;
    }
    __syncthreads();
    {
        const int col = tid;                          // 0-based column
        const int r   = p[col + 1] - 1;               // 0-based matched row
        if (r >= 0 && r < N) out[r * N + col] = 1.0f;
    }
}

// Dynamic SMEM size: C cache + solver state
#define SMEM_BYTES (CROWS * 256 * 4 + 2 * (N + 1) * 4 + 4 * (N + 1) * 4 \
                    + 2 * N * 4 + 4)

extern "C" void kernel_launch(void* const* d_in, const int* in_sizes, int n_in,
                              void* d_out, int out_size) {
    (void)in_sizes; (void)n_in; (void)out_size;
    cudaFuncSetAttribute(lap_jv16, cudaFuncAttributeMaxDynamicSharedMemorySize,
                         SMEM_BYTES);
    lap_jv16<<<1, 256, SMEM_BYTES>>>((const float*)d_in[0], (float*)d_out);
}